// round 13
// baseline (speedup 1.0000x reference)
#include <cuda_runtime.h>
#include <cuda_fp16.h>
#include <cstdint>

#define NROWS 8192
#define KCODES 8192
#define HD 256
#define KP 256           // approx K: fp16 leading planes only
#define MT 128           // rows per CTA
#define NTT 128          // codes per CTA
#define KCH 64           // fp16 per K chunk (128 B/row)
#define NCH 4            // 256/64
#define TPB 256
#define SLACK 2e-3f

// smem offsets (bytes): per stage A=16KB, B=16KB, double buffered
#define SA0 0
#define SB0 16384
#define SA1 32768
#define SB1 49152
#define SRED 65536
#define SMEMSZ 66560

__device__ __align__(128) __half g_H0[(size_t)NROWS * KP];
__device__ __align__(128) __half g_C0[(size_t)KCODES * KP];
__device__ float  g_hsq[NROWS];
__device__ float  g_csq[KCODES];
__device__ float2 g_herr[NROWS];    // (||h0||, ||e_h||)
__device__ float2 g_cerr[KCODES];   // (||f_c||, ||c0||+||f_c||)
__device__ unsigned int       g_minub[NROWS];
__device__ unsigned long long g_best[NROWS];

__device__ __forceinline__ uint32_t smem_u32(const void* p) {
    uint32_t a;
    asm("{ .reg .u64 t; cvta.to.shared.u64 t, %1; cvt.u32.u64 %0, t; }"
        : "=r"(a) : "l"(p));
    return a;
}
__device__ __forceinline__ void cp16(uint32_t dst, const void* src) {
    asm volatile("cp.async.cg.shared.global [%0], [%1], 16;"
                 :: "r"(dst), "l"(src) : "memory");
}
__device__ __forceinline__ void cp_commit() {
    asm volatile("cp.async.commit_group;" ::: "memory");
}
__device__ __forceinline__ void ldsm4(uint32_t* r, uint32_t a) {
    asm volatile("ldmatrix.sync.aligned.m8n8.x4.shared.b16 {%0,%1,%2,%3}, [%4];"
                 : "=r"(r[0]), "=r"(r[1]), "=r"(r[2]), "=r"(r[3]) : "r"(a));
}
__device__ __forceinline__ void mma16816(float* c, const uint32_t* a, const uint32_t* b) {
    asm volatile("mma.sync.aligned.m16n8k16.row.col.f32.f16.f16.f32 "
                 "{%0,%1,%2,%3}, {%4,%5,%6,%7}, {%8,%9}, {%0,%1,%2,%3};"
                 : "+f"(c[0]), "+f"(c[1]), "+f"(c[2]), "+f"(c[3])
                 : "r"(a[0]), "r"(a[1]), "r"(a[2]), "r"(a[3]), "r"(b[0]), "r"(b[1]));
}
__device__ __forceinline__ uint32_t pack_h2(float a, float b) {
    __half2 h = __floats2half2_rn(a, b);
    return *(uint32_t*)&h;
}

// k0: fp16 leading planes + norms + error coefficients + inits (one warp per row)
__global__ void prep_kernel(const float* __restrict__ h, const float* __restrict__ cb) {
    int row  = blockIdx.x * 8 + (threadIdx.x >> 5);
    int lane = threadIdx.x & 31;
    int which = row >= NROWS;            // 0: h row, 1: codebook row
    int r = which ? row - NROWS : row;
    const float* src = (which ? cb : h) + (size_t)r * HD;
    __half* dst = (which ? g_C0 : g_H0) + (size_t)r * KP;

    float s = 0.f, s0 = 0.f, se = 0.f;
#pragma unroll
    for (int i = 0; i < 2; i++) {
        float4 v = *(const float4*)(src + (lane + 32 * i) * 4);
        float f[4] = {v.x, v.y, v.z, v.w};
        float lo[4];
#pragma unroll
        for (int j = 0; j < 4; j++) {
            __half p0 = __float2half_rn(f[j]);
            lo[j] = __half2float(p0);
            float e = f[j] - lo[j];
            s  += f[j] * f[j];
            s0 += lo[j] * lo[j];
            se += e * e;
        }
        uint32_t q0[2] = {pack_h2(lo[0], lo[1]), pack_h2(lo[2], lo[3])};
        *(uint2*)(dst + (lane + 32 * i) * 4) = *(uint2*)q0;
    }
#pragma unroll
    for (int o = 16; o; o >>= 1) {
        s  += __shfl_xor_sync(0xffffffffu, s,  o);
        s0 += __shfl_xor_sync(0xffffffffu, s0, o);
        se += __shfl_xor_sync(0xffffffffu, se, o);
    }
    if (lane == 0) {
        float n0 = sqrtf(s0) * 1.0001f;
        float ne = sqrtf(se) * 1.0001f + 1e-12f;
        if (which) { g_csq[r] = s; g_cerr[r] = make_float2(ne, n0 + ne); }
        else       { g_hsq[r] = s; g_herr[r] = make_float2(n0, ne);
                     g_minub[r] = 0xFFFFFFFFu; g_best[r] = ~0ULL; }
    }
}

__device__ __forceinline__ float exact_dist(const float* __restrict__ h,
                                            const float* __restrict__ cb,
                                            int row, int code, float hv, float cv) {
    const float4* hp = (const float4*)(h  + (size_t)row  * HD);
    const float4* cp = (const float4*)(cb + (size_t)code * HD);
    double s = 0.0;
#pragma unroll 8
    for (int i = 0; i < 64; i++) {
        float4 a = hp[i], b = cp[i];
        s += (double)a.x * b.x + (double)a.y * b.y
           + (double)a.z * b.z + (double)a.w * b.w;
    }
    float dot = (float)s;
    return __fadd_rn(__fsub_rn(hv, 2.0f * dot), cv);
}

// k1: fp16 HMMA GEMM (K=256, 128x128 tile, 2 CTAs/SM)
// PASS_B=false: epilogue computes min over codes of (dist+err) -> g_minub
// PASS_B=true : epilogue tests (dist-err) <= minUB, rescores candidates exactly
template <bool PASS_B>
__global__ void __launch_bounds__(TPB, 2) vq_mma_kernel(const float* __restrict__ hin,
                                                        const float* __restrict__ cbin) {
    extern __shared__ char smem[];
    const uint32_t sb = smem_u32(smem);
    unsigned int* sredA       = (unsigned int*)(smem + SRED);
    unsigned long long* sredB = (unsigned long long*)(smem + SRED);

    const int tid  = threadIdx.x;
    const int wid  = tid >> 5;
    const int lane = tid & 31;

    if (PASS_B) { if (tid < MT) sredB[tid] = ~0ULL; }
    else        { if (tid < MT) sredA[tid] = 0xFFFFFFFFu; }

    const int bid   = blockIdx.x;
    const int panel = bid >> 9;
    const int mtile = (bid >> 3) & 63;
    const int ntile = (panel << 3) | (bid & 7);
    const int rbase = mtile * MT;
    const int cbase = ntile * NTT;

    const int wm = (wid >> 2) * 64;
    const int wn = (wid & 3) * 32;

    float acc[4][4][4];
#pragma unroll
    for (int a = 0; a < 4; a++)
#pragma unroll
        for (int b = 0; b < 4; b++)
#pragma unroll
            for (int c = 0; c < 4; c++) acc[a][b][c] = 0.f;

    auto load_chunk = [&](int ch, int buf) {
        const __half* As = g_H0 + (size_t)rbase * KP + ch * KCH;
        const __half* Bs = g_C0 + (size_t)cbase * KP + ch * KCH;
        uint32_t Ad = sb + (buf ? SA1 : SA0);
        uint32_t Bd = sb + (buf ? SB1 : SB0);
#pragma unroll
        for (int j = 0; j < 4; j++) {
            int u = tid + j * TPB;
            int r = u >> 3, c = u & 7;
            int d = r * 128 + ((c * 16) ^ ((r & 7) * 16));
            cp16(Ad + d, As + (size_t)r * KP + c * 8);
            cp16(Bd + d, Bs + (size_t)r * KP + c * 8);
        }
        cp_commit();
    };

    load_chunk(0, 0);
    load_chunk(1, 1);

#pragma unroll 1
    for (int ch = 0; ch < NCH; ch++) {
        if (ch == NCH - 1) asm volatile("cp.async.wait_group 0;" ::: "memory");
        else               asm volatile("cp.async.wait_group 1;" ::: "memory");
        __syncthreads();

        const uint32_t Ab = sb + ((ch & 1) ? SA1 : SA0);
        const uint32_t Bb = sb + ((ch & 1) ? SB1 : SB0);

#pragma unroll
        for (int k0 = 0; k0 < 4; k0++) {
            uint32_t af[4][4], bf[2][4];
            {
                int r = lane & 15;
                int cb16 = k0 * 32 + ((lane >> 4) & 1) * 16;
#pragma unroll
                for (int mi = 0; mi < 4; mi++) {
                    int row = wm + mi * 16 + r;
                    ldsm4(af[mi], Ab + row * 128 + (cb16 ^ ((row & 7) * 16)));
                }
            }
            {
                int nr = ((lane >> 4) & 1) * 8 + (lane & 7);
                int cb16 = k0 * 32 + ((lane >> 3) & 1) * 16;
#pragma unroll
                for (int nj = 0; nj < 2; nj++) {
                    int n = wn + nj * 16 + nr;
                    ldsm4(bf[nj], Bb + n * 128 + (cb16 ^ ((n & 7) * 16)));
                }
            }
#pragma unroll
            for (int mi = 0; mi < 4; mi++)
#pragma unroll
                for (int ni = 0; ni < 4; ni++)
                    mma16816(acc[mi][ni], af[mi], bf[ni >> 1] + (ni & 1) * 2);
        }
        __syncthreads();
        if (ch + 2 < NCH) load_chunk(ch + 2, ch & 1);
    }

    // epilogue
    const int qr = lane >> 2;
    const int qc = lane & 3;
#pragma unroll
    for (int mi = 0; mi < 4; mi++) {
#pragma unroll
        for (int half = 0; half < 2; half++) {
            int rl = wm + mi * 16 + qr + 8 * half;
            float hv = g_hsq[rbase + rl];
            float2 he = g_herr[rbase + rl];
            float minub;
            if (PASS_B)
                minub = __uint_as_float(g_minub[rbase + rl]) + 1e-4f;
            unsigned int ubmin = 0xFFFFFFFFu;
#pragma unroll
            for (int ni = 0; ni < 4; ni++) {
#pragma unroll
                for (int e = 0; e < 2; e++) {
                    int cg = cbase + wn + ni * 8 + 2 * qc + e;
                    float d = acc[mi][ni][half * 2 + e];
                    float cv = __ldg(&g_csq[cg]);
                    float2 ce = __ldg(&g_cerr[cg]);
                    float dist = __fadd_rn(__fsub_rn(hv, 2.0f * d), cv);
                    float err2 = 2.0f * (he.x * ce.x + he.y * ce.y) + SLACK;
                    if (PASS_B) {
                        if (dist - err2 <= minub) {
                            float ed = exact_dist(hin, cbin, rbase + rl, cg, hv, cv);
                            unsigned long long pk =
                                ((unsigned long long)__float_as_uint(ed) << 32) |
                                (unsigned)cg;
                            atomicMin(&sredB[rl], pk);
                        }
                    } else {
                        unsigned int ub = __float_as_uint(dist + err2);
                        if (ub < ubmin) ubmin = ub;
                    }
                }
            }
            if (!PASS_B) {
#pragma unroll
                for (int off = 1; off <= 2; off <<= 1) {
                    unsigned int o = __shfl_xor_sync(0xffffffffu, ubmin, off);
                    if (o < ubmin) ubmin = o;
                }
                if (qc == 0) atomicMin(&sredA[rl], ubmin);
            }
        }
    }
    __syncthreads();
    if (PASS_B) { if (tid < MT) atomicMin(&g_best[rbase + tid], sredB[tid]); }
    else        { if (tid < MT) atomicMin(&g_minub[rbase + tid], sredA[tid]); }
}

// k2: zero + one-hot scatter, loss fused into warp 0
__global__ void fill_kernel(const float* __restrict__ h, const float* __restrict__ cb,
                            float* __restrict__ out, int K, int N) {
    int row = blockIdx.x;
    int idx = (int)(g_best[row] & 0xffffffffu);
    int tid = threadIdx.x;

    if (tid < 32) {
        const float4* hp = (const float4*)(h  + (size_t)row * HD);
        const float4* cp = (const float4*)(cb + (size_t)idx * HD);
        float s = 0.f;
#pragma unroll
        for (int i = 0; i < 2; i++) {
            float4 a = hp[tid + 32 * i];
            float4 b = cp[tid + 32 * i];
            float dx = a.x - b.x, dy = a.y - b.y, dz = a.z - b.z, dw = a.w - b.w;
            s += dx * dx + dy * dy + dz * dz + dw * dw;
        }
#pragma unroll
        for (int o = 16; o; o >>= 1) s += __shfl_xor_sync(0xffffffffu, s, o);
        if (tid == 0) out[(size_t)N * K + row] = s * (1.25f / 256.0f);
    }

    float4* o = (float4*)(out + (size_t)row * K);
    int nf4 = K >> 2;
    for (int u = tid; u < nf4; u += blockDim.x) {
        int c = u << 2;
        float4 v;
        v.x = (c     == idx) ? 1.f : 0.f;
        v.y = (c + 1 == idx) ? 1.f : 0.f;
        v.z = (c + 2 == idx) ? 1.f : 0.f;
        v.w = (c + 3 == idx) ? 1.f : 0.f;
        __stcs(o + u, v);
    }
}

extern "C" void kernel_launch(void* const* d_in, const int* in_sizes, int n_in,
                              void* d_out, int out_size) {
    const float* h  = (const float*)d_in[0];
    const float* cb = (const float*)d_in[2];   // d_in[1] = temperature (unused)
    float* out = (float*)d_out;

    int N = in_sizes[0] / HD;   // 8192
    int K = in_sizes[2] / HD;   // 8192

    static int attr_done = 0;
    if (!attr_done) {
        cudaFuncSetAttribute(vq_mma_kernel<false>,
                             cudaFuncAttributeMaxDynamicSharedMemorySize, SMEMSZ);
        cudaFuncSetAttribute(vq_mma_kernel<true>,
                             cudaFuncAttributeMaxDynamicSharedMemorySize, SMEMSZ);
        attr_done = 1;
    }

    int grid = (NROWS / MT) * (KCODES / NTT);
    prep_kernel<<<(N + K) / 8, TPB>>>(h, cb);
    vq_mma_kernel<false><<<grid, TPB, SMEMSZ>>>(h, cb);
    vq_mma_kernel<true><<<grid, TPB, SMEMSZ>>>(h, cb);
    fill_kernel<<<N, TPB>>>(h, cb, out, K, N);
}

// round 14
// speedup vs baseline: 3.6822x; 3.6822x over previous
#include <cuda_runtime.h>
#include <cuda_fp16.h>
#include <cstdint>

#define NROWS 8192
#define KCODES 8192
#define HD 256
#define KP 256           // approx K: fp16 leading planes only
#define MT 128           // rows per CTA
#define NTT 128          // codes per CTA
#define KCH 64           // fp16 per K chunk (128 B/row)
#define NCH 4            // 256/64
#define TPB 256
#define SLACK 2e-3f
#define CAP (1 << 21)    // candidate list capacity (2M)

// smem offsets (bytes): per stage A=16KB, B=16KB, double buffered
#define SA0 0
#define SB0 16384
#define SA1 32768
#define SB1 49152
#define SRED 65536
#define SMEMSZ 66560

__device__ __align__(128) __half g_H0[(size_t)NROWS * KP];
__device__ __align__(128) __half g_C0[(size_t)KCODES * KP];
__device__ float  g_hsq[NROWS];
__device__ float  g_csq[KCODES];
__device__ float2 g_herr[NROWS];    // (||h0||, ||e_h||)
__device__ float2 g_cerr[KCODES];   // (||f_c||, ||c0||+||f_c||)
__device__ unsigned int       g_minub[NROWS];
__device__ unsigned long long g_best[NROWS];
__device__ int  g_ncand;
__device__ int2 g_cand[CAP];

__device__ __forceinline__ uint32_t smem_u32(const void* p) {
    uint32_t a;
    asm("{ .reg .u64 t; cvta.to.shared.u64 t, %1; cvt.u32.u64 %0, t; }"
        : "=r"(a) : "l"(p));
    return a;
}
__device__ __forceinline__ void cp16(uint32_t dst, const void* src) {
    asm volatile("cp.async.cg.shared.global [%0], [%1], 16;"
                 :: "r"(dst), "l"(src) : "memory");
}
__device__ __forceinline__ void cp_commit() {
    asm volatile("cp.async.commit_group;" ::: "memory");
}
__device__ __forceinline__ void ldsm4(uint32_t* r, uint32_t a) {
    asm volatile("ldmatrix.sync.aligned.m8n8.x4.shared.b16 {%0,%1,%2,%3}, [%4];"
                 : "=r"(r[0]), "=r"(r[1]), "=r"(r[2]), "=r"(r[3]) : "r"(a));
}
__device__ __forceinline__ void mma16816(float* c, const uint32_t* a, const uint32_t* b) {
    asm volatile("mma.sync.aligned.m16n8k16.row.col.f32.f16.f16.f32 "
                 "{%0,%1,%2,%3}, {%4,%5,%6,%7}, {%8,%9}, {%0,%1,%2,%3};"
                 : "+f"(c[0]), "+f"(c[1]), "+f"(c[2]), "+f"(c[3])
                 : "r"(a[0]), "r"(a[1]), "r"(a[2]), "r"(a[3]), "r"(b[0]), "r"(b[1]));
}
__device__ __forceinline__ uint32_t pack_h2(float a, float b) {
    __half2 h = __floats2half2_rn(a, b);
    return *(uint32_t*)&h;
}

// k0: fp16 leading planes + norms + error coefficients + inits (one warp per row)
__global__ void prep_kernel(const float* __restrict__ h, const float* __restrict__ cb) {
    if (blockIdx.x == 0 && threadIdx.x == 0) g_ncand = 0;
    int row  = blockIdx.x * 8 + (threadIdx.x >> 5);
    int lane = threadIdx.x & 31;
    int which = row >= NROWS;            // 0: h row, 1: codebook row
    int r = which ? row - NROWS : row;
    const float* src = (which ? cb : h) + (size_t)r * HD;
    __half* dst = (which ? g_C0 : g_H0) + (size_t)r * KP;

    float s = 0.f, s0 = 0.f, se = 0.f;
#pragma unroll
    for (int i = 0; i < 2; i++) {
        float4 v = *(const float4*)(src + (lane + 32 * i) * 4);
        float f[4] = {v.x, v.y, v.z, v.w};
        float lo[4];
#pragma unroll
        for (int j = 0; j < 4; j++) {
            __half p0 = __float2half_rn(f[j]);
            lo[j] = __half2float(p0);
            float e = f[j] - lo[j];
            s  += f[j] * f[j];
            s0 += lo[j] * lo[j];
            se += e * e;
        }
        uint32_t q0[2] = {pack_h2(lo[0], lo[1]), pack_h2(lo[2], lo[3])};
        *(uint2*)(dst + (lane + 32 * i) * 4) = *(uint2*)q0;
    }
#pragma unroll
    for (int o = 16; o; o >>= 1) {
        s  += __shfl_xor_sync(0xffffffffu, s,  o);
        s0 += __shfl_xor_sync(0xffffffffu, s0, o);
        se += __shfl_xor_sync(0xffffffffu, se, o);
    }
    if (lane == 0) {
        float n0 = sqrtf(s0) * 1.0001f;
        float ne = sqrtf(se) * 1.0001f + 1e-12f;
        if (which) { g_csq[r] = s; g_cerr[r] = make_float2(ne, n0 + ne); }
        else       { g_hsq[r] = s; g_herr[r] = make_float2(n0, ne);
                     g_minub[r] = 0xFFFFFFFFu; g_best[r] = ~0ULL; }
    }
}

// k1: fp16 HMMA GEMM (K=256, 128x128 tile, 2 CTAs/SM)
// MODE 0: epilogue -> per-row min(dist+err) into g_minub
// MODE 1: epilogue -> append (row, code) with dist-err <= minUB to g_cand
template <int MODE>
__global__ void __launch_bounds__(TPB, 2) vq_mma_kernel() {
    extern __shared__ char smem[];
    const uint32_t sb = smem_u32(smem);
    unsigned int* sredA = (unsigned int*)(smem + SRED);

    const int tid  = threadIdx.x;
    const int wid  = tid >> 5;
    const int lane = tid & 31;

    if (MODE == 0 && tid < MT) sredA[tid] = 0xFFFFFFFFu;

    const int bid   = blockIdx.x;
    const int panel = bid >> 9;
    const int mtile = (bid >> 3) & 63;
    const int ntile = (panel << 3) | (bid & 7);
    const int rbase = mtile * MT;
    const int cbase = ntile * NTT;

    const int wm = (wid >> 2) * 64;
    const int wn = (wid & 3) * 32;

    float acc[4][4][4];
#pragma unroll
    for (int a = 0; a < 4; a++)
#pragma unroll
        for (int b = 0; b < 4; b++)
#pragma unroll
            for (int c = 0; c < 4; c++) acc[a][b][c] = 0.f;

    auto load_chunk = [&](int ch, int buf) {
        const __half* As = g_H0 + (size_t)rbase * KP + ch * KCH;
        const __half* Bs = g_C0 + (size_t)cbase * KP + ch * KCH;
        uint32_t Ad = sb + (buf ? SA1 : SA0);
        uint32_t Bd = sb + (buf ? SB1 : SB0);
#pragma unroll
        for (int j = 0; j < 4; j++) {
            int u = tid + j * TPB;
            int r = u >> 3, c = u & 7;
            int d = r * 128 + ((c * 16) ^ ((r & 7) * 16));
            cp16(Ad + d, As + (size_t)r * KP + c * 8);
            cp16(Bd + d, Bs + (size_t)r * KP + c * 8);
        }
        cp_commit();
    };

    load_chunk(0, 0);
    load_chunk(1, 1);

#pragma unroll 1
    for (int ch = 0; ch < NCH; ch++) {
        if (ch == NCH - 1) asm volatile("cp.async.wait_group 0;" ::: "memory");
        else               asm volatile("cp.async.wait_group 1;" ::: "memory");
        __syncthreads();

        const uint32_t Ab = sb + ((ch & 1) ? SA1 : SA0);
        const uint32_t Bb = sb + ((ch & 1) ? SB1 : SB0);

#pragma unroll
        for (int k0 = 0; k0 < 4; k0++) {
            uint32_t af[4][4], bf[2][4];
            {
                int r = lane & 15;
                int cb16 = k0 * 32 + ((lane >> 4) & 1) * 16;
#pragma unroll
                for (int mi = 0; mi < 4; mi++) {
                    int row = wm + mi * 16 + r;
                    ldsm4(af[mi], Ab + row * 128 + (cb16 ^ ((row & 7) * 16)));
                }
            }
            {
                int nr = ((lane >> 4) & 1) * 8 + (lane & 7);
                int cb16 = k0 * 32 + ((lane >> 3) & 1) * 16;
#pragma unroll
                for (int nj = 0; nj < 2; nj++) {
                    int n = wn + nj * 16 + nr;
                    ldsm4(bf[nj], Bb + n * 128 + (cb16 ^ ((n & 7) * 16)));
                }
            }
#pragma unroll
            for (int mi = 0; mi < 4; mi++)
#pragma unroll
                for (int ni = 0; ni < 4; ni++)
                    mma16816(acc[mi][ni], af[mi], bf[ni >> 1] + (ni & 1) * 2);
        }
        __syncthreads();
        if (ch + 2 < NCH) load_chunk(ch + 2, ch & 1);
    }

    // epilogue
    const int qr = lane >> 2;
    const int qc = lane & 3;
#pragma unroll
    for (int mi = 0; mi < 4; mi++) {
#pragma unroll
        for (int half = 0; half < 2; half++) {
            int rl = wm + mi * 16 + qr + 8 * half;
            float hv = g_hsq[rbase + rl];
            float2 he = g_herr[rbase + rl];
            float minub = 0.f;
            if (MODE == 1)
                minub = __uint_as_float(g_minub[rbase + rl]) + 1e-4f;
            unsigned int ubmin = 0xFFFFFFFFu;
#pragma unroll
            for (int ni = 0; ni < 4; ni++) {
#pragma unroll
                for (int e = 0; e < 2; e++) {
                    int cg = cbase + wn + ni * 8 + 2 * qc + e;
                    float d = acc[mi][ni][half * 2 + e];
                    float cv = __ldg(&g_csq[cg]);
                    float2 ce = __ldg(&g_cerr[cg]);
                    float dist = __fadd_rn(__fsub_rn(hv, 2.0f * d), cv);
                    float err2 = 2.0f * (he.x * ce.x + he.y * ce.y) + SLACK;
                    if (MODE == 1) {
                        if (dist - err2 <= minub) {
                            int slot = atomicAdd(&g_ncand, 1);
                            if (slot < CAP)
                                g_cand[slot] = make_int2(rbase + rl, cg);
                        }
                    } else {
                        unsigned int ub = __float_as_uint(dist + err2);
                        if (ub < ubmin) ubmin = ub;
                    }
                }
            }
            if (MODE == 0) {
#pragma unroll
                for (int off = 1; off <= 2; off <<= 1) {
                    unsigned int o = __shfl_xor_sync(0xffffffffu, ubmin, off);
                    if (o < ubmin) ubmin = o;
                }
                if (qc == 0) atomicMin(&sredA[rl], ubmin);
            }
        }
    }
    if (MODE == 0) {
        __syncthreads();
        if (tid < MT) atomicMin(&g_minub[rbase + tid], sredA[tid]);
    }
}

// k2: exact fp64 rescore of candidates (one warp per candidate)
__global__ void rescore_kernel(const float* __restrict__ h,
                               const float* __restrict__ cb) {
    int cnt = g_ncand; if (cnt > CAP) cnt = CAP;
    int nw = gridDim.x * (TPB / 32);
    int w  = blockIdx.x * (TPB / 32) + (threadIdx.x >> 5);
    int lane = threadIdx.x & 31;
    for (int i = w; i < cnt; i += nw) {
        int2 rc = g_cand[i];
        const float4* hp = (const float4*)(h  + (size_t)rc.x * HD);
        const float4* cp = (const float4*)(cb + (size_t)rc.y * HD);
        double s = 0.0;
#pragma unroll
        for (int j = 0; j < 2; j++) {
            float4 a = hp[lane + 32 * j];
            float4 b = cp[lane + 32 * j];
            s += (double)a.x * b.x + (double)a.y * b.y
               + (double)a.z * b.z + (double)a.w * b.w;
        }
#pragma unroll
        for (int o = 16; o; o >>= 1) s += __shfl_xor_sync(0xffffffffu, s, o);
        if (lane == 0) {
            float dot = (float)s;
            float dist = __fadd_rn(__fsub_rn(g_hsq[rc.x], 2.0f * dot),
                                   g_csq[rc.y]);
            unsigned long long pk =
                ((unsigned long long)__float_as_uint(dist) << 32) | (unsigned)rc.y;
            atomicMin(&g_best[rc.x], pk);
        }
    }
}

// k3: zero + one-hot scatter, loss fused into warp 0
__global__ void fill_kernel(const float* __restrict__ h, const float* __restrict__ cb,
                            float* __restrict__ out, int K, int N) {
    int row = blockIdx.x;
    int idx = (int)(g_best[row] & 0xffffffffu);
    int tid = threadIdx.x;

    if (tid < 32) {
        const float4* hp = (const float4*)(h  + (size_t)row * HD);
        const float4* cp = (const float4*)(cb + (size_t)idx * HD);
        float s = 0.f;
#pragma unroll
        for (int i = 0; i < 2; i++) {
            float4 a = hp[tid + 32 * i];
            float4 b = cp[tid + 32 * i];
            float dx = a.x - b.x, dy = a.y - b.y, dz = a.z - b.z, dw = a.w - b.w;
            s += dx * dx + dy * dy + dz * dz + dw * dw;
        }
#pragma unroll
        for (int o = 16; o; o >>= 1) s += __shfl_xor_sync(0xffffffffu, s, o);
        if (tid == 0) out[(size_t)N * K + row] = s * (1.25f / 256.0f);
    }

    float4* o = (float4*)(out + (size_t)row * K);
    int nf4 = K >> 2;
    for (int u = tid; u < nf4; u += blockDim.x) {
        int c = u << 2;
        float4 v;
        v.x = (c     == idx) ? 1.f : 0.f;
        v.y = (c + 1 == idx) ? 1.f : 0.f;
        v.z = (c + 2 == idx) ? 1.f : 0.f;
        v.w = (c + 3 == idx) ? 1.f : 0.f;
        __stcs(o + u, v);
    }
}

extern "C" void kernel_launch(void* const* d_in, const int* in_sizes, int n_in,
                              void* d_out, int out_size) {
    const float* h  = (const float*)d_in[0];
    const float* cb = (const float*)d_in[2];   // d_in[1] = temperature (unused)
    float* out = (float*)d_out;

    int N = in_sizes[0] / HD;   // 8192
    int K = in_sizes[2] / HD;   // 8192

    static int attr_done = 0;
    if (!attr_done) {
        cudaFuncSetAttribute(vq_mma_kernel<0>,
                             cudaFuncAttributeMaxDynamicSharedMemorySize, SMEMSZ);
        cudaFuncSetAttribute(vq_mma_kernel<1>,
                             cudaFuncAttributeMaxDynamicSharedMemorySize, SMEMSZ);
        attr_done = 1;
    }

    int grid = (NROWS / MT) * (KCODES / NTT);
    prep_kernel<<<(N + K) / 8, TPB>>>(h, cb);
    vq_mma_kernel<0><<<grid, TPB, SMEMSZ>>>();
    vq_mma_kernel<1><<<grid, TPB, SMEMSZ>>>();
    rescore_kernel<<<256, TPB>>>(h, cb);
    fill_kernel<<<N, TPB>>>(h, cb, out, K, N);
}

// round 16
// speedup vs baseline: 5.1084x; 1.3873x over previous
#include <cuda_runtime.h>
#include <cuda_fp16.h>
#include <cstdint>

#define NROWS 8192
#define KCODES 8192
#define HD 256
#define KP 768           // expanded K: 3 fp16 segments of 256 (h0c0 + h0c1 + h1c0)
#define MT 128           // rows per CTA
#define NTT 128          // codes per CTA
#define KCH 64           // fp16 per K chunk (128 B/row)
#define NCH 12           // 768/64
#define TPB 256

// smem: 3 stages x (A 16KB + B 16KB) = 96KB, then reduction buffer
#define STAGE 32768
#define SRED  98304
#define SMEMSZ 99328

__device__ __align__(128) __half g_HA[(size_t)NROWS * KP];
__device__ __align__(128) __half g_CBH[(size_t)KCODES * KP];
__device__ float g_hsq[NROWS];
__device__ float g_csq[KCODES];
__device__ unsigned long long g_best[NROWS];

__device__ __forceinline__ uint32_t smem_u32(const void* p) {
    uint32_t a;
    asm("{ .reg .u64 t; cvta.to.shared.u64 t, %1; cvt.u32.u64 %0, t; }"
        : "=r"(a) : "l"(p));
    return a;
}
__device__ __forceinline__ void cp16(uint32_t dst, const void* src) {
    asm volatile("cp.async.cg.shared.global [%0], [%1], 16;"
                 :: "r"(dst), "l"(src) : "memory");
}
__device__ __forceinline__ void cp_commit() {
    asm volatile("cp.async.commit_group;" ::: "memory");
}
__device__ __forceinline__ void ldsm4(uint32_t* r, uint32_t a) {
    asm volatile("ldmatrix.sync.aligned.m8n8.x4.shared.b16 {%0,%1,%2,%3}, [%4];"
                 : "=r"(r[0]), "=r"(r[1]), "=r"(r[2]), "=r"(r[3]) : "r"(a));
}
__device__ __forceinline__ void mma16816(float* c, const uint32_t* a, const uint32_t* b) {
    asm volatile("mma.sync.aligned.m16n8k16.row.col.f32.f16.f16.f32 "
                 "{%0,%1,%2,%3}, {%4,%5,%6,%7}, {%8,%9}, {%0,%1,%2,%3};"
                 : "+f"(c[0]), "+f"(c[1]), "+f"(c[2]), "+f"(c[3])
                 : "r"(a[0]), "r"(a[1]), "r"(a[2]), "r"(a[3]), "r"(b[0]), "r"(b[1]));
}
__device__ __forceinline__ uint32_t pack_h2(float a, float b) {
    __half2 h = __floats2half2_rn(a, b);
    return *(uint32_t*)&h;
}

// k0: fused split-plane build + row norms + g_best init (one warp per row)
__global__ void prep_kernel(const float* __restrict__ h, const float* __restrict__ cb) {
    int row  = blockIdx.x * 8 + (threadIdx.x >> 5);
    int lane = threadIdx.x & 31;
    int which = row >= NROWS;            // 0: h row, 1: codebook row
    int r = which ? row - NROWS : row;
    const float* src = (which ? cb : h) + (size_t)r * HD;
    __half* dst = (which ? g_CBH : g_HA) + (size_t)r * KP;

    float s = 0.f;
#pragma unroll
    for (int i = 0; i < 2; i++) {
        float4 v = *(const float4*)(src + (lane + 32 * i) * 4);
        s += v.x * v.x + v.y * v.y + v.z * v.z + v.w * v.w;
        float f[4] = {v.x, v.y, v.z, v.w};
        float lo[4], hi[4];
#pragma unroll
        for (int j = 0; j < 4; j++) {
            __half p0 = __float2half_rn(f[j]);
            lo[j] = __half2float(p0);
            hi[j] = f[j] - lo[j];
        }
        uint32_t q0[2] = {pack_h2(lo[0], lo[1]), pack_h2(lo[2], lo[3])};
        uint32_t q1[2] = {pack_h2(hi[0], hi[1]), pack_h2(hi[2], hi[3])};
        int e = (lane + 32 * i) * 4;
        // h: [h0, h0, h1]   cb: [c0, c1, c0]
        *(uint2*)(dst + e)       = *(uint2*)q0;
        *(uint2*)(dst + 256 + e) = which ? *(uint2*)q1 : *(uint2*)q0;
        *(uint2*)(dst + 512 + e) = which ? *(uint2*)q0 : *(uint2*)q1;
    }
#pragma unroll
    for (int o = 16; o; o >>= 1) s += __shfl_xor_sync(0xffffffffu, s, o);
    if (lane == 0) { if (which) g_csq[r] = s; else g_hsq[r] = s; }
    if (!which && lane == 1) g_best[r] = ~0ULL;
}

// k1: fp16 HMMA GEMM (K=768, 128x128 tile, 2 CTAs/SM, 3-stage pipeline)
__global__ void __launch_bounds__(TPB, 2) vq_mma_kernel() {
    extern __shared__ char smem[];
    const uint32_t sb = smem_u32(smem);
    unsigned long long* sred = (unsigned long long*)(smem + SRED);

    const int tid  = threadIdx.x;
    const int wid  = tid >> 5;
    const int lane = tid & 31;

    if (tid < MT) sred[tid] = ~0ULL;

    // panel-swizzled coords: 8-wide n panels for L2 reuse
    const int bid   = blockIdx.x;
    const int panel = bid >> 9;               // 0..7
    const int mtile = (bid >> 3) & 63;        // 0..63
    const int ntile = (panel << 3) | (bid & 7);
    const int rbase = mtile * MT;
    const int cbase = ntile * NTT;

    const int wm = (wid >> 2) * 64;   // warp row offset (0,64)
    const int wn = (wid & 3) * 32;    // warp col offset (0..96)

    float acc[4][4][4];
#pragma unroll
    for (int a = 0; a < 4; a++)
#pragma unroll
        for (int b = 0; b < 4; b++)
#pragma unroll
            for (int c = 0; c < 4; c++) acc[a][b][c] = 0.f;

    auto load_chunk = [&](int ch, int st) {
        const __half* As = g_HA  + (size_t)rbase * KP + ch * KCH;
        const __half* Bs = g_CBH + (size_t)cbase * KP + ch * KCH;
        uint32_t Ad = sb + st * STAGE;
        uint32_t Bd = sb + st * STAGE + 16384;
#pragma unroll
        for (int j = 0; j < 4; j++) {
            int u = tid + j * TPB;            // 0..1023
            int r = u >> 3, c = u & 7;
            int d = r * 128 + ((c * 16) ^ ((r & 7) * 16));
            cp16(Ad + d, As + (size_t)r * KP + c * 8);
            cp16(Bd + d, Bs + (size_t)r * KP + c * 8);
        }
        cp_commit();
    };

    load_chunk(0, 0);
    load_chunk(1, 1);

#pragma unroll 1
    for (int ch = 0; ch < NCH; ch++) {
        if (ch == NCH - 1) asm volatile("cp.async.wait_group 0;" ::: "memory");
        else               asm volatile("cp.async.wait_group 1;" ::: "memory");
        __syncthreads();
        // prefetch into the stage freed by chunk ch-1 (safe: all warps passed sync)
        if (ch + 2 < NCH) load_chunk(ch + 2, (ch + 2) % 3);

        const int st = ch % 3;
        const uint32_t Ab = sb + st * STAGE;
        const uint32_t Bb = sb + st * STAGE + 16384;

#pragma unroll
        for (int k0 = 0; k0 < 4; k0++) {
            uint32_t af[4][4], bf[2][4];
            {
                int r = lane & 15;
                int cb16 = k0 * 32 + ((lane >> 4) & 1) * 16;
#pragma unroll
                for (int mi = 0; mi < 4; mi++) {
                    int row = wm + mi * 16 + r;
                    ldsm4(af[mi], Ab + row * 128 + (cb16 ^ ((row & 7) * 16)));
                }
            }
            {
                int nr = ((lane >> 4) & 1) * 8 + (lane & 7);
                int cb16 = k0 * 32 + ((lane >> 3) & 1) * 16;
#pragma unroll
                for (int nj = 0; nj < 2; nj++) {
                    int n = wn + nj * 16 + nr;
                    ldsm4(bf[nj], Bb + n * 128 + (cb16 ^ ((n & 7) * 16)));
                }
            }
#pragma unroll
            for (int mi = 0; mi < 4; mi++)
#pragma unroll
                for (int ni = 0; ni < 4; ni++)
                    mma16816(acc[mi][ni], af[mi], bf[ni >> 1] + (ni & 1) * 2);
        }
        // no trailing sync: next iteration's wait+sync provides the barrier
    }

    // epilogue: dist = (hsq - 2*dot) + csq, packed argmin
    const int qr = lane >> 2;
    const int qc = lane & 3;
#pragma unroll
    for (int mi = 0; mi < 4; mi++) {
#pragma unroll
        for (int half = 0; half < 2; half++) {
            int rl = wm + mi * 16 + qr + 8 * half;
            float hv = g_hsq[rbase + rl];
            float bv = 3.4e38f;
            int   bi = 0x7fffffff;
#pragma unroll
            for (int ni = 0; ni < 4; ni++) {
#pragma unroll
                for (int e = 0; e < 2; e++) {
                    int cg = cbase + wn + ni * 8 + 2 * qc + e;
                    float d = acc[mi][ni][half * 2 + e];
                    float dist = __fadd_rn(__fsub_rn(hv, 2.0f * d), __ldg(&g_csq[cg]));
                    if (dist < bv || (dist == bv && cg < bi)) { bv = dist; bi = cg; }
                }
            }
            unsigned long long pk =
                ((unsigned long long)__float_as_uint(bv) << 32) | (unsigned)bi;
#pragma unroll
            for (int off = 1; off <= 2; off <<= 1) {
                unsigned long long o = __shfl_xor_sync(0xffffffffu, pk, off);
                if (o < pk) pk = o;
            }
            if (qc == 0) atomicMin(&sred[rl], pk);
        }
    }
    __syncthreads();
    if (tid < MT) atomicMin(&g_best[rbase + tid], sred[tid]);
}

// k2: zero + one-hot scatter, loss fused into warp 0
__global__ void fill_kernel(const float* __restrict__ h, const float* __restrict__ cb,
                            float* __restrict__ out, int K, int N) {
    int row = blockIdx.x;
    int idx = (int)(g_best[row] & 0xffffffffu);
    int tid = threadIdx.x;

    if (tid < 32) {  // warp 0: loss = 1.25 * mean((h - z_q)^2)
        const float4* hp = (const float4*)(h  + (size_t)row * HD);
        const float4* cp = (const float4*)(cb + (size_t)idx * HD);
        float s = 0.f;
#pragma unroll
        for (int i = 0; i < 2; i++) {
            float4 a = hp[tid + 32 * i];
            float4 b = cp[tid + 32 * i];
            float dx = a.x - b.x, dy = a.y - b.y, dz = a.z - b.z, dw = a.w - b.w;
            s += dx * dx + dy * dy + dz * dz + dw * dw;
        }
#pragma unroll
        for (int o = 16; o; o >>= 1) s += __shfl_xor_sync(0xffffffffu, s, o);
        if (tid == 0) out[(size_t)N * K + row] = s * (1.25f / 256.0f);
    }

    float4* o = (float4*)(out + (size_t)row * K);
    int nf4 = K >> 2;
    for (int u = tid; u < nf4; u += blockDim.x) {
        int c = u << 2;
        float4 v;
        v.x = (c     == idx) ? 1.f : 0.f;
        v.y = (c + 1 == idx) ? 1.f : 0.f;
        v.z = (c + 2 == idx) ? 1.f : 0.f;
        v.w = (c + 3 == idx) ? 1.f : 0.f;
        __stcs(o + u, v);
    }
}

extern "C" void kernel_launch(void* const* d_in, const int* in_sizes, int n_in,
                              void* d_out, int out_size) {
    const float* h  = (const float*)d_in[0];
    const float* cb = (const float*)d_in[2];   // d_in[1] = temperature (unused)
    float* out = (float*)d_out;

    int N = in_sizes[0] / HD;   // 8192
    int K = in_sizes[2] / HD;   // 8192

    static int attr_done = 0;
    if (!attr_done) {
        cudaFuncSetAttribute(vq_mma_kernel,
                             cudaFuncAttributeMaxDynamicSharedMemorySize, SMEMSZ);
        attr_done = 1;
    }

    prep_kernel<<<(N + K) / 8, TPB>>>(h, cb);
    vq_mma_kernel<<<(NROWS / MT) * (KCODES / NTT), TPB, SMEMSZ>>>();
    fill_kernel<<<N, TPB>>>(h, cb, out, K, N);
}